// round 14
// baseline (speedup 1.0000x reference)
#include <cuda_runtime.h>
#include <math.h>

typedef unsigned long long ull;

// ---------------------------------------------------------------------------
// Problem constants
// ---------------------------------------------------------------------------
#define NROWS 2048
#define INV_T 5.0f
#define ZS 8

// scratch layout (floats)
#define O_Q1   0          // 2048*200
#define O_K1   409600
#define O_Q    819200     // 2048*50
#define O_K    921600
#define O_TQ   1024000
#define O_TK   1126400
#define O_H2   1228800    // 2048*200
#define O_HK2  1638400
#define O_X    2048000    // 2048*60
#define O_PQ   2170880    // 8 * 2048*200 split-K partials (q)
#define O_PK   5447680
#define SCRATCH_FLOATS 8724480

static __device__ float g_scratch[SCRATCH_FLOATS];

// ---------------------------------------------------------------------------
// Packed f32x2 helpers (Blackwell FFMA2 — only reachable via PTX)
// ---------------------------------------------------------------------------
__device__ __forceinline__ ull pack_dup(float a) {
    ull d;
    asm("mov.b64 %0, {%1, %1};" : "=l"(d) : "f"(a));
    return d;
}
__device__ __forceinline__ void fma2(ull& c, ull a, ull b) {
    asm("fma.rn.f32x2 %0, %1, %2, %3;" : "=l"(c) : "l"(a), "l"(b), "l"(c));
}
__device__ __forceinline__ float2 unpack2(ull v) {
    float lo, hi;
    asm("mov.b64 {%0, %1}, %2;" : "=f"(lo), "=f"(hi) : "l"(v));
    return make_float2(lo, hi);
}

// ---------------------------------------------------------------------------
// Guarded vector loads
// ---------------------------------------------------------------------------
__device__ __forceinline__ float4 ldgA_guard(const float* p, int k, int kEnd) {
    if (k + 3 < kEnd) return *(const float4*)p;
    float4 v = make_float4(0.f, 0.f, 0.f, 0.f);
    if (k     < kEnd) v.x = p[0];
    if (k + 1 < kEnd) v.y = p[1];
    if (k + 2 < kEnd) v.z = p[2];
    if (k + 3 < kEnd) v.w = p[3];
    return v;
}
__device__ __forceinline__ float4 ldgB_guard(const float* p, int krow, int kEnd,
                                             int col, int N) {
    float4 v = make_float4(0.f, 0.f, 0.f, 0.f);
    if (krow < kEnd) {
        if (col + 3 < N) return *(const float4*)p;
        if (col     < N) v.x = p[0];
        if (col + 1 < N) v.y = p[1];
        if (col + 2 < N) v.z = p[2];
        if (col + 3 < N) v.w = p[3];
    }
    return v;
}

// ===========================================================================
// BIG GEMM (encoder split-K): 128x64 tile, 8x4/thread — measured-best (R11).
// ===========================================================================
#define GBM 128
#define GBN 64
#define GBK 16
#define APAD 132

__device__ __forceinline__ void bgemm_core(const float* __restrict__ A,
                                           const float* __restrict__ B,
                                           float* __restrict__ C,
                                           int M, int N, int K,
                                           int kStart, int kEnd)
{
    __shared__ __align__(16) float As[2][GBK][APAD];
    __shared__ __align__(16) float Bs[2][GBK][GBN];

    const int tid  = threadIdx.x;
    const int row0 = blockIdx.y * GBM;
    const int col0 = blockIdx.x * GBN;
    const int tx = tid & 15;
    const int ty = tid >> 4;
    const int am  = tid >> 2;
    const int akc = tid & 3;
    const int bkk = tid >> 4;
    const int bnc = tid & 15;

    ull acc[4][4] = {};
    const int nT = (kEnd - kStart + GBK - 1) / GBK;

    float4 pa0, pa1, pb;
    {
        int ka = kStart + akc * 4;
        pa0 = ldgA_guard(A + (size_t)(row0 + am)      * K + ka, ka, kEnd);
        pa1 = ldgA_guard(A + (size_t)(row0 + am + 64) * K + ka, ka, kEnd);
        int kb = kStart + bkk, cb = col0 + bnc * 4;
        pb  = ldgB_guard(B + (size_t)kb * N + cb, kb, kEnd, cb, N);
    }

    int buf = 0;
    for (int t = 0; t < nT; t++) {
        As[buf][akc * 4 + 0][am] = pa0.x;
        As[buf][akc * 4 + 1][am] = pa0.y;
        As[buf][akc * 4 + 2][am] = pa0.z;
        As[buf][akc * 4 + 3][am] = pa0.w;
        As[buf][akc * 4 + 0][am + 64] = pa1.x;
        As[buf][akc * 4 + 1][am + 64] = pa1.y;
        As[buf][akc * 4 + 2][am + 64] = pa1.z;
        As[buf][akc * 4 + 3][am + 64] = pa1.w;
        *(float4*)&Bs[buf][bkk][bnc * 4] = pb;
        __syncthreads();

        if (t + 1 < nT) {
            int k0 = kStart + (t + 1) * GBK;
            int ka = k0 + akc * 4;
            pa0 = ldgA_guard(A + (size_t)(row0 + am)      * K + ka, ka, kEnd);
            pa1 = ldgA_guard(A + (size_t)(row0 + am + 64) * K + ka, ka, kEnd);
            int kb = k0 + bkk, cb = col0 + bnc * 4;
            pb  = ldgB_guard(B + (size_t)kb * N + cb, kb, kEnd, cb, N);
        }

#pragma unroll
        for (int kk = 0; kk < GBK; kk++) {
            longlong2 A0 = *(const longlong2*)&As[buf][kk][ty * 8];
            longlong2 A1 = *(const longlong2*)&As[buf][kk][ty * 8 + 4];
            ull ap0 = (ull)A0.x, ap1 = (ull)A0.y;
            ull ap2 = (ull)A1.x, ap3 = (ull)A1.y;
#pragma unroll
            for (int j = 0; j < 4; j++) {
                ull bd = pack_dup(Bs[buf][kk][tx * 4 + j]);
                fma2(acc[0][j], ap0, bd);
                fma2(acc[1][j], ap1, bd);
                fma2(acc[2][j], ap2, bd);
                fma2(acc[3][j], ap3, bd);
            }
        }
        buf ^= 1;
        // single barrier per tile: a thread is at most one barrier ahead and
        // adjacent iterations touch different buffers => race-free.
    }

#pragma unroll
    for (int p = 0; p < 4; p++) {
        int r = row0 + ty * 8 + 2 * p;
#pragma unroll
        for (int j = 0; j < 4; j++) {
            int c = col0 + tx * 4 + j;
            if (c >= N) continue;
            float2 v = unpack2(acc[p][j]);
            C[(size_t)r * N + c]       = v.x;
            C[(size_t)(r + 1) * N + c] = v.y;
        }
    }
}

__global__ void __launch_bounds__(256, 3)
bgemm_splitk(const float* __restrict__ A, const float* __restrict__ B,
             float* __restrict__ C, int M, int N, int K, int chunk)
{
    int z  = blockIdx.z;
    int ks = z * chunk;
    int ke = ks + chunk; if (ke > K) ke = K;
    bgemm_core(A, B, C + (size_t)z * M * N, M, N, K, ks, ke);
}

// ===========================================================================
// XGEMM (decoders): 128x128 tile, BK=16, 256 threads, 8x8 per thread.
//  - 32 FFMA2 per k-step per thread => fma-pipe-bound, not issue-bound
//  - vectorized STG.128 epilogue on full column tiles (sector-efficient)
//  - requires M % 128 == 0 (M = 2048 here)
// ===========================================================================
#define XBM 128
#define XBN 128
#define XBK 16
#define XAPAD 132

__global__ void __launch_bounds__(256)
xgemm_act(const float* __restrict__ A, const float* __restrict__ B,
          const float* __restrict__ bias, float* __restrict__ C,
          int M, int N, int K, int act)
{
    __shared__ __align__(16) float As[2][XBK][XAPAD];
    __shared__ __align__(16) float Bs[2][XBK][XBN];

    const int tid  = threadIdx.x;
    const int row0 = blockIdx.y * XBM;
    const int col0 = blockIdx.x * XBN;
    const int tx = tid & 15;    // 8 cols: col0 + tx*8 + j
    const int ty = tid >> 4;    // 8 rows: row0 + ty*8 + i

    // A staging: e = tid + l*256 (l=0,1) -> arow = e>>2 (0..127), akc = e&3
    const int arow = tid >> 2;
    const int akc  = tid & 3;
    // B staging: bkk = e>>5 (0..15), bnc = e&31 (4-col group)
    const int bkk = tid >> 5;
    const int bnc = tid & 31;

    ull acc[4][8] = {};   // [row-pair 0..3][col 0..7]

    const int nT = (K + XBK - 1) / XBK;

    float4 pa0, pa1, pb0, pb1;
    {
        int ka = akc * 4;
        pa0 = ldgA_guard(A + (size_t)(row0 + arow)      * K + ka, ka, K);
        pa1 = ldgA_guard(A + (size_t)(row0 + arow + 64) * K + ka, ka, K);
        int cb = col0 + bnc * 4;
        pb0 = ldgB_guard(B + (size_t)bkk       * N + cb, bkk,     K, cb, N);
        pb1 = ldgB_guard(B + (size_t)(bkk + 8) * N + cb, bkk + 8, K, cb, N);
    }

    int buf = 0;
    for (int t = 0; t < nT; t++) {
        As[buf][akc * 4 + 0][arow] = pa0.x;
        As[buf][akc * 4 + 1][arow] = pa0.y;
        As[buf][akc * 4 + 2][arow] = pa0.z;
        As[buf][akc * 4 + 3][arow] = pa0.w;
        As[buf][akc * 4 + 0][arow + 64] = pa1.x;
        As[buf][akc * 4 + 1][arow + 64] = pa1.y;
        As[buf][akc * 4 + 2][arow + 64] = pa1.z;
        As[buf][akc * 4 + 3][arow + 64] = pa1.w;
        *(float4*)&Bs[buf][bkk][bnc * 4]     = pb0;
        *(float4*)&Bs[buf][bkk + 8][bnc * 4] = pb1;
        __syncthreads();

        if (t + 1 < nT) {
            int k0 = (t + 1) * XBK;
            int ka = k0 + akc * 4;
            pa0 = ldgA_guard(A + (size_t)(row0 + arow)      * K + ka, ka, K);
            pa1 = ldgA_guard(A + (size_t)(row0 + arow + 64) * K + ka, ka, K);
            int cb = col0 + bnc * 4;
            pb0 = ldgB_guard(B + (size_t)(k0 + bkk)     * N + cb, k0 + bkk,     K, cb, N);
            pb1 = ldgB_guard(B + (size_t)(k0 + bkk + 8) * N + cb, k0 + bkk + 8, K, cb, N);
        }

#pragma unroll
        for (int kk = 0; kk < XBK; kk++) {
            longlong2 A0 = *(const longlong2*)&As[buf][kk][ty * 8];
            longlong2 A1 = *(const longlong2*)&As[buf][kk][ty * 8 + 4];
            ull ap0 = (ull)A0.x, ap1 = (ull)A0.y;
            ull ap2 = (ull)A1.x, ap3 = (ull)A1.y;
            float4 b0 = *(const float4*)&Bs[buf][kk][tx * 8];
            float4 b1 = *(const float4*)&Bs[buf][kk][tx * 8 + 4];
            ull bd[8];
            bd[0] = pack_dup(b0.x); bd[1] = pack_dup(b0.y);
            bd[2] = pack_dup(b0.z); bd[3] = pack_dup(b0.w);
            bd[4] = pack_dup(b1.x); bd[5] = pack_dup(b1.y);
            bd[6] = pack_dup(b1.z); bd[7] = pack_dup(b1.w);
#pragma unroll
            for (int j = 0; j < 8; j++) {
                fma2(acc[0][j], ap0, bd[j]);
                fma2(acc[1][j], ap1, bd[j]);
                fma2(acc[2][j], ap2, bd[j]);
                fma2(acc[3][j], ap3, bd[j]);
            }
        }
        buf ^= 1;
    }

    // epilogue: bias + act, vectorized stores when the whole tile is in-range
    const bool fullN = (col0 + XBN <= N);
    float bv[8];
#pragma unroll
    for (int j = 0; j < 8; j++) {
        int c = col0 + tx * 8 + j;
        bv[j] = (c < N) ? bias[c] : 0.0f;
    }

#pragma unroll
    for (int p = 0; p < 4; p++) {
        int r = row0 + ty * 8 + 2 * p;
        float vx[8], vy[8];
#pragma unroll
        for (int j = 0; j < 8; j++) {
            float2 v = unpack2(acc[p][j]);
            v.x += bv[j]; v.y += bv[j];
            if (act == 1)      { v.x = fmaxf(v.x, 0.f); v.y = fmaxf(v.y, 0.f); }
            else if (act == 2) { v.x = 1.f / (1.f + __expf(-v.x));
                                 v.y = 1.f / (1.f + __expf(-v.y)); }
            vx[j] = v.x; vy[j] = v.y;
        }
        if (fullN) {
            float* r0p = C + (size_t)r * N + col0 + tx * 8;
            float* r1p = C + (size_t)(r + 1) * N + col0 + tx * 8;
            *(float4*)(r0p)     = make_float4(vx[0], vx[1], vx[2], vx[3]);
            *(float4*)(r0p + 4) = make_float4(vx[4], vx[5], vx[6], vx[7]);
            *(float4*)(r1p)     = make_float4(vy[0], vy[1], vy[2], vy[3]);
            *(float4*)(r1p + 4) = make_float4(vy[4], vy[5], vy[6], vy[7]);
        } else {
#pragma unroll
            for (int j = 0; j < 8; j++) {
                int c = col0 + tx * 8 + j;
                if (c >= N) continue;
                C[(size_t)r * N + c]       = vx[j];
                C[(size_t)(r + 1) * N + c] = vy[j];
            }
        }
    }
}

// ---------------------------------------------------------------------------
// Split-K reduction + bias + relu, batched over 2 jobs.
// ---------------------------------------------------------------------------
struct RedJobs {
    const float* P[2];
    const float* bias[2];
    float*       C[2];
};
__global__ void reduce_splitk(RedJobs jobs, int M, int N)
{
    int j = blockIdx.z;
    int idx = blockIdx.x * blockDim.x + threadIdx.x;
    int total = (M * N) >> 2;
    if (idx >= total) return;

    const float4* P = (const float4*)jobs.P[j];
    float4 s = P[idx];
#pragma unroll
    for (int z = 1; z < ZS; z++) {
        float4 a = P[idx + (size_t)z * total];
        s.x += a.x; s.y += a.y; s.z += a.z; s.w += a.w;
    }
    int col = (idx * 4) % N;
    const float* bi = jobs.bias[j] + col;
    s.x = fmaxf(s.x + bi[0], 0.0f);
    s.y = fmaxf(s.y + bi[1], 0.0f);
    s.z = fmaxf(s.z + bi[2], 0.0f);
    s.w = fmaxf(s.w + bi[3], 0.0f);
    ((float4*)jobs.C[j])[idx] = s;
}

// ===========================================================================
// Fused small chain (unchanged from R11)
// ===========================================================================
struct ChainSide {
    const float* in;
    const float *w2, *b2, *w3, *b3, *wl, *bl, *wd1, *bd1, *wd2, *bd2;
    float *outQ, *outT, *outH;
};
struct ChainArgs { ChainSide s[2]; };

#define CH_SMEM_FLOATS (12800 + 12800 + 10200 + 256)
#define CH_SMEM_BYTES  (CH_SMEM_FLOATS * 4)

__device__ __forceinline__ void chain_loadW(float* wbuf, float* bbuf,
                                            const float* W, int n,
                                            const float* b, int nb)
{
    int tid = threadIdx.x;
    const float4* W4 = (const float4*)W;
    int n4 = n >> 2;
    for (int e = tid; e < n4; e += 256) ((float4*)wbuf)[e] = W4[e];
    for (int e = tid; e < nb; e += 256) bbuf[e] = b[e];
}

__device__ __forceinline__ void chain_layer(const float* X, int nin, int nout,
                                            int act, float* Y,
                                            float* g, int gld, int row0,
                                            const float* wbuf, const float* bbuf)
{
    int tid = threadIdx.x;
    int tx = tid & 15, ty = tid >> 4;
    int nct = (nout + 63) >> 6;
    for (int ct = 0; ct < nct; ct++) {
        float acc[4][4] = {};
        int cbase = ct * 64 + tx * 4;
#pragma unroll 2
        for (int k = 0; k < nin; k++) {
            float a0 = X[(ty * 4 + 0) * 200 + k];
            float a1 = X[(ty * 4 + 1) * 200 + k];
            float a2 = X[(ty * 4 + 2) * 200 + k];
            float a3 = X[(ty * 4 + 3) * 200 + k];
            const float* wr = &wbuf[k * nout + cbase];
            float b0 = wr[0], b1 = wr[1], b2 = wr[2], b3 = wr[3];
            acc[0][0] += a0 * b0; acc[0][1] += a0 * b1; acc[0][2] += a0 * b2; acc[0][3] += a0 * b3;
            acc[1][0] += a1 * b0; acc[1][1] += a1 * b1; acc[1][2] += a1 * b2; acc[1][3] += a1 * b3;
            acc[2][0] += a2 * b0; acc[2][1] += a2 * b1; acc[2][2] += a2 * b2; acc[2][3] += a2 * b3;
            acc[3][0] += a3 * b0; acc[3][1] += a3 * b1; acc[3][2] += a3 * b2; acc[3][3] += a3 * b3;
        }
#pragma unroll
        for (int i = 0; i < 4; i++) {
#pragma unroll
            for (int j = 0; j < 4; j++) {
                int c = cbase + j;
                if (c >= nout) continue;
                float v = acc[i][j] + bbuf[c];
                if (act == 1) v = fmaxf(v, 0.0f);
                if (Y) Y[(ty * 4 + i) * 200 + c] = v;
                if (g) g[(size_t)(row0 + ty * 4 + i) * gld + c] = v;
            }
        }
    }
}

__global__ void __launch_bounds__(256)
chain_kernel(ChainArgs args)
{
    extern __shared__ float smch[];
    float* bufA = smch;
    float* bufB = smch + 12800;
    float* wbuf = smch + 25600;
    float* bbuf = smch + 35800;

    ChainSide cs = args.s[blockIdx.y];
    int row0 = blockIdx.x * 64;
    int tid = threadIdx.x;

    {
        const float4* in4 = (const float4*)(cs.in + (size_t)row0 * 200);
        for (int e = tid; e < 64 * 50; e += 256) ((float4*)bufA)[e] = in4[e];
    }
    chain_loadW(wbuf, bbuf, cs.w2, 200 * 50, cs.b2, 50);
    __syncthreads();
    chain_layer(bufA, 200, 50, 1, bufB, nullptr, 0, row0, wbuf, bbuf);
    __syncthreads();
    chain_loadW(wbuf, bbuf, cs.w3, 2500, cs.b3, 50);
    __syncthreads();
    chain_layer(bufB, 50, 50, 0, bufA, cs.outQ, 50, row0, wbuf, bbuf);
    __syncthreads();
    chain_loadW(wbuf, bbuf, cs.wl, 2500, cs.bl, 50);
    __syncthreads();
    chain_layer(bufA, 50, 50, 0, nullptr, cs.outT, 50, row0, wbuf, bbuf);
    __syncthreads();
    chain_loadW(wbuf, bbuf, cs.wd1, 2500, cs.bd1, 50);
    __syncthreads();
    chain_layer(bufA, 50, 50, 1, bufB, nullptr, 0, row0, wbuf, bbuf);
    __syncthreads();
    chain_loadW(wbuf, bbuf, cs.wd2, 50 * 200, cs.bd2, 200);
    __syncthreads();
    chain_layer(bufB, 50, 200, 1, nullptr, cs.outH, 200, row0, wbuf, bbuf);
}

// ---------------------------------------------------------------------------
// Warp-per-row fuse_X (unchanged)
// ---------------------------------------------------------------------------
__global__ void fuse_X_kernel(const float* __restrict__ q,
                              const float* __restrict__ k,
                              const float* __restrict__ tq,
                              const float* __restrict__ tk,
                              float* __restrict__ X)
{
    int row  = (blockIdx.x * blockDim.x + threadIdx.x) >> 5;
    int lane = threadIdx.x & 31;
    if (row >= NROWS) return;

    const float* qr  = q  + row * 50;
    const float* kr  = k  + row * 50;
    const float* tqr = tq + row * 50;
    const float* tkr = tk + row * 50;
    float* xr = X + row * 60;

    float s0 = qr[lane] + kr[lane];
    float s1 = 0.0f;
    if (lane < 18) s1 = qr[lane + 32] + kr[lane + 32];
    float ss = s0 * s0 + s1 * s1;
#pragma unroll
    for (int o = 16; o > 0; o >>= 1)
        ss += __shfl_xor_sync(0xFFFFFFFFu, ss, o);
    float inv = 1.0f / fmaxf(sqrtf(ss), 1e-12f);
    xr[lane] = s0 * inv;
    if (lane < 18) xr[lane + 32] = s1 * inv;

    if (lane < 10) {
        float t = 0.0f;
#pragma unroll
        for (int g = 0; g < 5; g++)
            t += tqr[g * 10 + lane] * tkr[g * 10 + lane];
        xr[50 + lane] = (t >= 0.0f) ? sqrtf(t) : -sqrtf(-t);
    }
}

// ---------------------------------------------------------------------------
// Contrastive logits (unchanged)
// ---------------------------------------------------------------------------
__global__ void logits_kernel(const float* __restrict__ q,
                              const float* __restrict__ k,
                              float* __restrict__ out)
{
    __shared__ __align__(16) float Qr[50][64];
    __shared__ __align__(16) float Qc[50][64];
    __shared__ __align__(16) float Kc[50][64];

    const int tid = threadIdx.x;
    const int r0 = blockIdx.y * 64;
    const int c0 = blockIdx.x * 64;

    for (int e = tid; e < 64 * 50; e += 256) {
        int r = e / 50, c = e % 50;
        Qr[c][r] = q[(r0 + r) * 50 + c];
        Qc[c][r] = q[(c0 + r) * 50 + c];
        Kc[c][r] = k[(c0 + r) * 50 + c];
    }
    __syncthreads();

    const int tx = tid & 15;
    const int ty = tid >> 4;

    ull g1[4][2] = {};
    ull g2[4][2] = {};

#pragma unroll 2
    for (int c = 0; c < 50; c++) {
        ull bq0 = *(const ull*)&Qc[c][tx * 4];
        ull bq1 = *(const ull*)&Qc[c][tx * 4 + 2];
        ull bk0 = *(const ull*)&Kc[c][tx * 4];
        ull bk1 = *(const ull*)&Kc[c][tx * 4 + 2];
#pragma unroll
        for (int i = 0; i < 4; i++) {
            ull ad = pack_dup(Qr[c][ty * 4 + i]);
            fma2(g1[i][0], ad, bq0);
            fma2(g1[i][1], ad, bq1);
            fma2(g2[i][0], ad, bk0);
            fma2(g2[i][1], ad, bk1);
        }
    }

#pragma unroll
    for (int i = 0; i < 4; i++) {
        int n = r0 + ty * 4 + i;
        float* rowp = out + (size_t)n * 4095;
        float2 a0 = unpack2(g1[i][0]), a1 = unpack2(g1[i][1]);
        float2 b0 = unpack2(g2[i][0]), b1 = unpack2(g2[i][1]);
        float v1[4] = {a0.x, a0.y, a1.x, a1.y};
        float v2[4] = {b0.x, b0.y, b1.x, b1.y};
#pragma unroll
        for (int j = 0; j < 4; j++) {
            int m = c0 + tx * 4 + j;
            if (m == n) {
                rowp[0] = v2[j] * INV_T;
            } else {
                int off = (m < n) ? m : m - 1;
                rowp[1 + off]    = v1[j] * INV_T;
                rowp[2048 + off] = v2[j] * INV_T;
            }
        }
    }
}

// ---------------------------------------------------------------------------
// Prototype logits + label zeroing (unchanged)
// ---------------------------------------------------------------------------
__global__ void proto_kernel(const float* __restrict__ X,
                             const float* __restrict__ P,
                             const int* __restrict__ c2c,
                             float* __restrict__ lp,
                             float* __restrict__ labels,
                             float* __restrict__ labels_p)
{
    __shared__ float Ps[64][60];
    __shared__ float Xs[4][60];

    const int tid = threadIdx.x;
    const int row0 = blockIdx.x * 4;

    for (int e = tid; e < 64 * 60; e += 256) Ps[e / 60][e % 60] = P[e];
    for (int e = tid; e < 4 * 60; e += 256)
        Xs[e / 60][e % 60] = X[(row0 + e / 60) * 60 + e % 60];
    __syncthreads();

    const int r = tid >> 6;
    const int c = tid & 63;
    const int n = row0 + r;

    float acc = 0.0f;
#pragma unroll
    for (int i = 0; i < 60; i++) acc += Xs[r][i] * Ps[c][i];

    const int cc = c2c[n];
    int pos = (c == cc) ? 0 : ((c < cc) ? c + 1 : c);
    lp[(size_t)n * 64 + pos] = acc;

    if (c == 0) {
        labels[n]   = 0.0f;
        labels_p[n] = 0.0f;
    }
}

// ---------------------------------------------------------------------------
// Launcher
// ---------------------------------------------------------------------------
extern "C" void kernel_launch(void* const* d_in, const int* in_sizes, int n_in,
                              void* d_out, int out_size)
{
    const float* omics_q = (const float*)d_in[0];
    const float* omics_k = (const float*)d_in[1];
    const float* protos  = (const float*)d_in[2];
    const float* re_w1 = (const float*)d_in[3];
    const float* re_b1 = (const float*)d_in[4];
    const float* re_w2 = (const float*)d_in[5];
    const float* re_b2 = (const float*)d_in[6];
    const float* re_w3 = (const float*)d_in[7];
    const float* re_b3 = (const float*)d_in[8];
    const float* rd_w1 = (const float*)d_in[9];
    const float* rd_b1 = (const float*)d_in[10];
    const float* rd_w2 = (const float*)d_in[11];
    const float* rd_b2 = (const float*)d_in[12];
    const float* rd_w3 = (const float*)d_in[13];
    const float* rd_b3 = (const float*)d_in[14];
    const float* me_w1 = (const float*)d_in[15];
    const float* me_b1 = (const float*)d_in[16];
    const float* me_w2 = (const float*)d_in[17];
    const float* me_b2 = (const float*)d_in[18];
    const float* me_w3 = (const float*)d_in[19];
    const float* me_b3 = (const float*)d_in[20];
    const float* md_w1 = (const float*)d_in[21];
    const float* md_b1 = (const float*)d_in[22];
    const float* md_w2 = (const float*)d_in[23];
    const float* md_b2 = (const float*)d_in[24];
    const float* md_w3 = (const float*)d_in[25];
    const float* md_b3 = (const float*)d_in[26];
    const float* lr_w  = (const float*)d_in[27];
    const float* lr_b  = (const float*)d_in[28];
    const float* lm_w  = (const float*)d_in[29];
    const float* lm_b  = (const float*)d_in[30];
    const int*   c2c   = (const int*)d_in[31];

    float* scratch = nullptr;
    cudaGetSymbolAddress((void**)&scratch, g_scratch);

    float* out    = (float*)d_out;
    float* rna    = out;                              // 2048*20000
    float* mirna  = out + 40960000;                   // 2048*2000
    float* logits = out + 45056000;                   // 2048*4095
    float* labels = out + 53442560;                   // 2048
    float* lproto = out + 53444608;                   // 2048*64
    float* lplab  = out + 53575680;                   // 2048

    // idempotent, called every invocation (no static guards allowed)
    cudaFuncSetAttribute(chain_kernel,
                         cudaFuncAttributeMaxDynamicSharedMemorySize,
                         CH_SMEM_BYTES);

    dim3 blk(256);

    // 1) encoder-L1 GEMMs, split-K=8
    bgemm_splitk<<<dim3(4, 16, ZS), blk>>>(omics_q, re_w1, scratch + O_PQ,
                                           NROWS, 200, 20000, 2512);
    bgemm_splitk<<<dim3(4, 16, ZS), blk>>>(omics_k, me_w1, scratch + O_PK,
                                           NROWS, 200, 2000, 256);
    // 2) split-K reduce + bias + relu
    {
        RedJobs rj;
        rj.P[0] = scratch + O_PQ; rj.bias[0] = re_b1; rj.C[0] = scratch + O_Q1;
        rj.P[1] = scratch + O_PK; rj.bias[1] = me_b1; rj.C[1] = scratch + O_K1;
        reduce_splitk<<<dim3(400, 1, 2), blk>>>(rj, NROWS, 200);
    }
    // 3) fused small chain
    {
        ChainArgs ca;
        ca.s[0] = { scratch + O_Q1, re_w2, re_b2, re_w3, re_b3, lr_w, lr_b,
                    rd_w1, rd_b1, rd_w2, rd_b2,
                    scratch + O_Q, scratch + O_TQ, scratch + O_H2 };
        ca.s[1] = { scratch + O_K1, me_w2, me_b2, me_w3, me_b3, lm_w, lm_b,
                    md_w1, md_b1, md_w2, md_b2,
                    scratch + O_K, scratch + O_TK, scratch + O_HK2 };
        chain_kernel<<<dim3(32, 2), blk, CH_SMEM_BYTES>>>(ca);
    }
    // 4) decoder L3: 128x128 tile xgemm with vectorized epilogue
    xgemm_act<<<dim3(157, 16), blk>>>(scratch + O_H2,  rd_w3, rd_b3, rna,
                                      NROWS, 20000, 200, 2);
    xgemm_act<<<dim3(16, 16),  blk>>>(scratch + O_HK2, md_w3, md_b3, mirna,
                                      NROWS, 2000, 200, 2);

    // 5) small epilogue kernels
    fuse_X_kernel<<<256, 256>>>(scratch + O_Q, scratch + O_K,
                                scratch + O_TQ, scratch + O_TK, scratch + O_X);
    logits_kernel<<<dim3(32, 32), blk>>>(scratch + O_Q, scratch + O_K, logits);
    proto_kernel<<<512, blk>>>(scratch + O_X, protos, c2c, lproto, labels, lplab);
}

// round 16
// speedup vs baseline: 1.1484x; 1.1484x over previous
#include <cuda_runtime.h>
#include <math.h>

typedef unsigned long long ull;

// ---------------------------------------------------------------------------
// Problem constants
// ---------------------------------------------------------------------------
#define NROWS 2048
#define INV_T 5.0f
#define ZS 7              // 4*16*7 = 448 blocks ~= 148 SMs * 3 blocks capacity

// scratch layout (floats)
#define O_Q1   0          // 2048*200
#define O_K1   409600
#define O_Q    819200     // 2048*50
#define O_K    921600
#define O_TQ   1024000
#define O_TK   1126400
#define O_H2   1228800    // 2048*200
#define O_HK2  1638400
#define O_X    2048000    // 2048*60
#define O_PQ   2170880    // up to 8 * 2048*200 split-K partials (q)
#define O_PK   5447680
#define SCRATCH_FLOATS 8724480

static __device__ float g_scratch[SCRATCH_FLOATS];

// ---------------------------------------------------------------------------
// Packed f32x2 helpers (Blackwell FFMA2 — only reachable via PTX)
// ---------------------------------------------------------------------------
__device__ __forceinline__ ull pack_dup(float a) {
    ull d;
    asm("mov.b64 %0, {%1, %1};" : "=l"(d) : "f"(a));
    return d;
}
__device__ __forceinline__ void fma2(ull& c, ull a, ull b) {
    asm("fma.rn.f32x2 %0, %1, %2, %3;" : "=l"(c) : "l"(a), "l"(b), "l"(c));
}
__device__ __forceinline__ float2 unpack2(ull v) {
    float lo, hi;
    asm("mov.b64 {%0, %1}, %2;" : "=f"(lo), "=f"(hi) : "l"(v));
    return make_float2(lo, hi);
}

// ===========================================================================
// BIG GEMM: 128x64 tile, BK=16, 256 threads, 8x4 per thread (measured-best).
//  - accumulators packed along M, A read from SMEM as packed f32x2 pairs
//  - double-buffered SMEM, register prefetch, ONE barrier per tile
// ===========================================================================
#define GBM 128
#define GBN 64
#define GBK 16
#define APAD 132

__device__ __forceinline__ float4 ldgA_guard(const float* p, int k, int kEnd) {
    if (k + 3 < kEnd) return *(const float4*)p;
    float4 v = make_float4(0.f, 0.f, 0.f, 0.f);
    if (k     < kEnd) v.x = p[0];
    if (k + 1 < kEnd) v.y = p[1];
    if (k + 2 < kEnd) v.z = p[2];
    if (k + 3 < kEnd) v.w = p[3];
    return v;
}
__device__ __forceinline__ float4 ldgB_guard(const float* p, int krow, int kEnd,
                                             int col, int N) {
    float4 v = make_float4(0.f, 0.f, 0.f, 0.f);
    if (krow < kEnd) {
        if (col + 3 < N) return *(const float4*)p;
        if (col     < N) v.x = p[0];
        if (col + 1 < N) v.y = p[1];
        if (col + 2 < N) v.z = p[2];
        if (col + 3 < N) v.w = p[3];
    }
    return v;
}

__device__ __forceinline__ void bgemm_core(const float* __restrict__ A,
                                           const float* __restrict__ B,
                                           const float* __restrict__ bias,
                                           float* __restrict__ C,
                                           int M, int N, int K, int act,
                                           int kStart, int kEnd, bool partial)
{
    __shared__ __align__(16) float As[2][GBK][APAD];
    __shared__ __align__(16) float Bs[2][GBK][GBN];

    const int tid  = threadIdx.x;
    const int row0 = blockIdx.y * GBM;
    const int col0 = blockIdx.x * GBN;
    const int tx = tid & 15;
    const int ty = tid >> 4;

    const int am  = tid >> 2;
    const int akc = tid & 3;
    const int bkk = tid >> 4;
    const int bnc = tid & 15;

    ull acc[4][4] = {};

    const int nT = (kEnd - kStart + GBK - 1) / GBK;

    float4 pa0, pa1, pb;
    {
        int ka = kStart + akc * 4;
        pa0 = ldgA_guard(A + (size_t)(row0 + am)      * K + ka, ka, kEnd);
        pa1 = ldgA_guard(A + (size_t)(row0 + am + 64) * K + ka, ka, kEnd);
        int kb = kStart + bkk, cb = col0 + bnc * 4;
        pb  = ldgB_guard(B + (size_t)kb * N + cb, kb, kEnd, cb, N);
    }

    int buf = 0;
    for (int t = 0; t < nT; t++) {
        As[buf][akc * 4 + 0][am] = pa0.x;
        As[buf][akc * 4 + 1][am] = pa0.y;
        As[buf][akc * 4 + 2][am] = pa0.z;
        As[buf][akc * 4 + 3][am] = pa0.w;
        As[buf][akc * 4 + 0][am + 64] = pa1.x;
        As[buf][akc * 4 + 1][am + 64] = pa1.y;
        As[buf][akc * 4 + 2][am + 64] = pa1.z;
        As[buf][akc * 4 + 3][am + 64] = pa1.w;
        *(float4*)&Bs[buf][bkk][bnc * 4] = pb;
        __syncthreads();

        if (t + 1 < nT) {
            int k0 = kStart + (t + 1) * GBK;
            int ka = k0 + akc * 4;
            pa0 = ldgA_guard(A + (size_t)(row0 + am)      * K + ka, ka, kEnd);
            pa1 = ldgA_guard(A + (size_t)(row0 + am + 64) * K + ka, ka, kEnd);
            int kb = k0 + bkk, cb = col0 + bnc * 4;
            pb  = ldgB_guard(B + (size_t)kb * N + cb, kb, kEnd, cb, N);
        }

#pragma unroll
        for (int kk = 0; kk < GBK; kk++) {
            longlong2 A0 = *(const longlong2*)&As[buf][kk][ty * 8];
            longlong2 A1 = *(const longlong2*)&As[buf][kk][ty * 8 + 4];
            ull ap0 = (ull)A0.x, ap1 = (ull)A0.y;
            ull ap2 = (ull)A1.x, ap3 = (ull)A1.y;
#pragma unroll
            for (int j = 0; j < 4; j++) {
                ull bd = pack_dup(Bs[buf][kk][tx * 4 + j]);
                fma2(acc[0][j], ap0, bd);
                fma2(acc[1][j], ap1, bd);
                fma2(acc[2][j], ap2, bd);
                fma2(acc[3][j], ap3, bd);
            }
        }
        buf ^= 1;
        // single barrier per tile: a thread is at most one barrier ahead and
        // adjacent iterations touch different buffers => race-free.
    }

#pragma unroll
    for (int p = 0; p < 4; p++) {
        int r = row0 + ty * 8 + 2 * p;
#pragma unroll
        for (int j = 0; j < 4; j++) {
            int c = col0 + tx * 4 + j;
            if (c >= N) continue;
            float2 v = unpack2(acc[p][j]);
            if (!partial) {
                float bb = bias[c];
                v.x += bb; v.y += bb;
                if (act == 1)      { v.x = fmaxf(v.x, 0.f); v.y = fmaxf(v.y, 0.f); }
                else if (act == 2) { v.x = 1.f / (1.f + __expf(-v.x));
                                     v.y = 1.f / (1.f + __expf(-v.y)); }
            }
            C[(size_t)r * N + c]       = v.x;
            C[(size_t)(r + 1) * N + c] = v.y;
        }
    }
}

__global__ void __launch_bounds__(256, 3)
bgemm_splitk(const float* __restrict__ A, const float* __restrict__ B,
             float* __restrict__ C, int M, int N, int K, int chunk)
{
    int z  = blockIdx.z;
    int ks = z * chunk;
    int ke = ks + chunk; if (ke > K) ke = K;
    bgemm_core(A, B, nullptr, C + (size_t)z * M * N, M, N, K, 0, ks, ke, true);
}

__global__ void __launch_bounds__(256, 3)
bgemm_act(const float* __restrict__ A, const float* __restrict__ B,
          const float* __restrict__ bias, float* __restrict__ C,
          int M, int N, int K, int act)
{
    bgemm_core(A, B, bias, C, M, N, K, act, 0, K, false);
}

// ---------------------------------------------------------------------------
// Split-K reduction (ZS partials) + bias + relu, batched over 2 jobs.
// ---------------------------------------------------------------------------
struct RedJobs {
    const float* P[2];
    const float* bias[2];
    float*       C[2];
};
__global__ void reduce_splitk(RedJobs jobs, int M, int N)
{
    int j = blockIdx.z;
    int idx = blockIdx.x * blockDim.x + threadIdx.x;
    int total = (M * N) >> 2;
    if (idx >= total) return;

    const float4* P = (const float4*)jobs.P[j];
    float4 s = P[idx];
#pragma unroll
    for (int z = 1; z < ZS; z++) {
        float4 a = P[idx + (size_t)z * total];
        s.x += a.x; s.y += a.y; s.z += a.z; s.w += a.w;
    }
    int col = (idx * 4) % N;
    const float* bi = jobs.bias[j] + col;
    s.x = fmaxf(s.x + bi[0], 0.0f);
    s.y = fmaxf(s.y + bi[1], 0.0f);
    s.z = fmaxf(s.z + bi[2], 0.0f);
    s.w = fmaxf(s.w + bi[3], 0.0f);
    ((float4*)jobs.C[j])[idx] = s;
}

// ===========================================================================
// Fused small chain (unchanged from R11)
// ===========================================================================
struct ChainSide {
    const float* in;
    const float *w2, *b2, *w3, *b3, *wl, *bl, *wd1, *bd1, *wd2, *bd2;
    float *outQ, *outT, *outH;
};
struct ChainArgs { ChainSide s[2]; };

#define CH_SMEM_FLOATS (12800 + 12800 + 10200 + 256)
#define CH_SMEM_BYTES  (CH_SMEM_FLOATS * 4)

__device__ __forceinline__ void chain_loadW(float* wbuf, float* bbuf,
                                            const float* W, int n,
                                            const float* b, int nb)
{
    int tid = threadIdx.x;
    const float4* W4 = (const float4*)W;
    int n4 = n >> 2;
    for (int e = tid; e < n4; e += 256) ((float4*)wbuf)[e] = W4[e];
    for (int e = tid; e < nb; e += 256) bbuf[e] = b[e];
}

__device__ __forceinline__ void chain_layer(const float* X, int nin, int nout,
                                            int act, float* Y,
                                            float* g, int gld, int row0,
                                            const float* wbuf, const float* bbuf)
{
    int tid = threadIdx.x;
    int tx = tid & 15, ty = tid >> 4;
    int nct = (nout + 63) >> 6;
    for (int ct = 0; ct < nct; ct++) {
        float acc[4][4] = {};
        int cbase = ct * 64 + tx * 4;
#pragma unroll 2
        for (int k = 0; k < nin; k++) {
            float a0 = X[(ty * 4 + 0) * 200 + k];
            float a1 = X[(ty * 4 + 1) * 200 + k];
            float a2 = X[(ty * 4 + 2) * 200 + k];
            float a3 = X[(ty * 4 + 3) * 200 + k];
            const float* wr = &wbuf[k * nout + cbase];
            float b0 = wr[0], b1 = wr[1], b2 = wr[2], b3 = wr[3];
            acc[0][0] += a0 * b0; acc[0][1] += a0 * b1; acc[0][2] += a0 * b2; acc[0][3] += a0 * b3;
            acc[1][0] += a1 * b0; acc[1][1] += a1 * b1; acc[1][2] += a1 * b2; acc[1][3] += a1 * b3;
            acc[2][0] += a2 * b0; acc[2][1] += a2 * b1; acc[2][2] += a2 * b2; acc[2][3] += a2 * b3;
            acc[3][0] += a3 * b0; acc[3][1] += a3 * b1; acc[3][2] += a3 * b2; acc[3][3] += a3 * b3;
        }
#pragma unroll
        for (int i = 0; i < 4; i++) {
#pragma unroll
            for (int j = 0; j < 4; j++) {
                int c = cbase + j;
                if (c >= nout) continue;
                float v = acc[i][j] + bbuf[c];
                if (act == 1) v = fmaxf(v, 0.0f);
                if (Y) Y[(ty * 4 + i) * 200 + c] = v;
                if (g) g[(size_t)(row0 + ty * 4 + i) * gld + c] = v;
            }
        }
    }
}

__global__ void __launch_bounds__(256)
chain_kernel(ChainArgs args)
{
    extern __shared__ float smch[];
    float* bufA = smch;
    float* bufB = smch + 12800;
    float* wbuf = smch + 25600;
    float* bbuf = smch + 35800;

    ChainSide cs = args.s[blockIdx.y];
    int row0 = blockIdx.x * 64;
    int tid = threadIdx.x;

    {
        const float4* in4 = (const float4*)(cs.in + (size_t)row0 * 200);
        for (int e = tid; e < 64 * 50; e += 256) ((float4*)bufA)[e] = in4[e];
    }
    chain_loadW(wbuf, bbuf, cs.w2, 200 * 50, cs.b2, 50);
    __syncthreads();
    chain_layer(bufA, 200, 50, 1, bufB, nullptr, 0, row0, wbuf, bbuf);
    __syncthreads();
    chain_loadW(wbuf, bbuf, cs.w3, 2500, cs.b3, 50);
    __syncthreads();
    chain_layer(bufB, 50, 50, 0, bufA, cs.outQ, 50, row0, wbuf, bbuf);
    __syncthreads();
    chain_loadW(wbuf, bbuf, cs.wl, 2500, cs.bl, 50);
    __syncthreads();
    chain_layer(bufA, 50, 50, 0, nullptr, cs.outT, 50, row0, wbuf, bbuf);
    __syncthreads();
    chain_loadW(wbuf, bbuf, cs.wd1, 2500, cs.bd1, 50);
    __syncthreads();
    chain_layer(bufA, 50, 50, 1, bufB, nullptr, 0, row0, wbuf, bbuf);
    __syncthreads();
    chain_loadW(wbuf, bbuf, cs.wd2, 50 * 200, cs.bd2, 200);
    __syncthreads();
    chain_layer(bufB, 50, 200, 1, nullptr, cs.outH, 200, row0, wbuf, bbuf);
}

// ---------------------------------------------------------------------------
// Warp-per-row fuse_X (unchanged)
// ---------------------------------------------------------------------------
__global__ void fuse_X_kernel(const float* __restrict__ q,
                              const float* __restrict__ k,
                              const float* __restrict__ tq,
                              const float* __restrict__ tk,
                              float* __restrict__ X)
{
    int row  = (blockIdx.x * blockDim.x + threadIdx.x) >> 5;
    int lane = threadIdx.x & 31;
    if (row >= NROWS) return;

    const float* qr  = q  + row * 50;
    const float* kr  = k  + row * 50;
    const float* tqr = tq + row * 50;
    const float* tkr = tk + row * 50;
    float* xr = X + row * 60;

    float s0 = qr[lane] + kr[lane];
    float s1 = 0.0f;
    if (lane < 18) s1 = qr[lane + 32] + kr[lane + 32];
    float ss = s0 * s0 + s1 * s1;
#pragma unroll
    for (int o = 16; o > 0; o >>= 1)
        ss += __shfl_xor_sync(0xFFFFFFFFu, ss, o);
    float inv = 1.0f / fmaxf(sqrtf(ss), 1e-12f);
    xr[lane] = s0 * inv;
    if (lane < 18) xr[lane + 32] = s1 * inv;

    if (lane < 10) {
        float t = 0.0f;
#pragma unroll
        for (int g = 0; g < 5; g++)
            t += tqr[g * 10 + lane] * tkr[g * 10 + lane];
        xr[50 + lane] = (t >= 0.0f) ? sqrtf(t) : -sqrtf(-t);
    }
}

// ---------------------------------------------------------------------------
// Contrastive logits (unchanged)
// ---------------------------------------------------------------------------
__global__ void logits_kernel(const float* __restrict__ q,
                              const float* __restrict__ k,
                              float* __restrict__ out)
{
    __shared__ __align__(16) float Qr[50][64];
    __shared__ __align__(16) float Qc[50][64];
    __shared__ __align__(16) float Kc[50][64];

    const int tid = threadIdx.x;
    const int r0 = blockIdx.y * 64;
    const int c0 = blockIdx.x * 64;

    for (int e = tid; e < 64 * 50; e += 256) {
        int r = e / 50, c = e % 50;
        Qr[c][r] = q[(r0 + r) * 50 + c];
        Qc[c][r] = q[(c0 + r) * 50 + c];
        Kc[c][r] = k[(c0 + r) * 50 + c];
    }
    __syncthreads();

    const int tx = tid & 15;
    const int ty = tid >> 4;

    ull g1[4][2] = {};
    ull g2[4][2] = {};

#pragma unroll 2
    for (int c = 0; c < 50; c++) {
        ull bq0 = *(const ull*)&Qc[c][tx * 4];
        ull bq1 = *(const ull*)&Qc[c][tx * 4 + 2];
        ull bk0 = *(const ull*)&Kc[c][tx * 4];
        ull bk1 = *(const ull*)&Kc[c][tx * 4 + 2];
#pragma unroll
        for (int i = 0; i < 4; i++) {
            ull ad = pack_dup(Qr[c][ty * 4 + i]);
            fma2(g1[i][0], ad, bq0);
            fma2(g1[i][1], ad, bq1);
            fma2(g2[i][0], ad, bk0);
            fma2(g2[i][1], ad, bk1);
        }
    }

#pragma unroll
    for (int i = 0; i < 4; i++) {
        int n = r0 + ty * 4 + i;
        float* rowp = out + (size_t)n * 4095;
        float2 a0 = unpack2(g1[i][0]), a1 = unpack2(g1[i][1]);
        float2 b0 = unpack2(g2[i][0]), b1 = unpack2(g2[i][1]);
        float v1[4] = {a0.x, a0.y, a1.x, a1.y};
        float v2[4] = {b0.x, b0.y, b1.x, b1.y};
#pragma unroll
        for (int j = 0; j < 4; j++) {
            int m = c0 + tx * 4 + j;
            if (m == n) {
                rowp[0] = v2[j] * INV_T;
            } else {
                int off = (m < n) ? m : m - 1;
                rowp[1 + off]    = v1[j] * INV_T;
                rowp[2048 + off] = v2[j] * INV_T;
            }
        }
    }
}

// ---------------------------------------------------------------------------
// Prototype logits + label zeroing (unchanged)
// ---------------------------------------------------------------------------
__global__ void proto_kernel(const float* __restrict__ X,
                             const float* __restrict__ P,
                             const int* __restrict__ c2c,
                             float* __restrict__ lp,
                             float* __restrict__ labels,
                             float* __restrict__ labels_p)
{
    __shared__ float Ps[64][60];
    __shared__ float Xs[4][60];

    const int tid = threadIdx.x;
    const int row0 = blockIdx.x * 4;

    for (int e = tid; e < 64 * 60; e += 256) Ps[e / 60][e % 60] = P[e];
    for (int e = tid; e < 4 * 60; e += 256)
        Xs[e / 60][e % 60] = X[(row0 + e / 60) * 60 + e % 60];
    __syncthreads();

    const int r = tid >> 6;
    const int c = tid & 63;
    const int n = row0 + r;

    float acc = 0.0f;
#pragma unroll
    for (int i = 0; i < 60; i++) acc += Xs[r][i] * Ps[c][i];

    const int cc = c2c[n];
    int pos = (c == cc) ? 0 : ((c < cc) ? c + 1 : c);
    lp[(size_t)n * 64 + pos] = acc;

    if (c == 0) {
        labels[n]   = 0.0f;
        labels_p[n] = 0.0f;
    }
}

// ---------------------------------------------------------------------------
// Launcher — R11 structure, split-K factor tuned to SM capacity (448 ~= 444)
// ---------------------------------------------------------------------------
extern "C" void kernel_launch(void* const* d_in, const int* in_sizes, int n_in,
                              void* d_out, int out_size)
{
    const float* omics_q = (const float*)d_in[0];
    const float* omics_k = (const float*)d_in[1];
    const float* protos  = (const float*)d_in[2];
    const float* re_w1 = (const float*)d_in[3];
    const float* re_b1 = (const float*)d_in[4];
    const float* re_w2 = (const float*)d_in[5];
    const float* re_b2 = (const float*)d_in[6];
    const float* re_w3 = (const float*)d_in[7];
    const float* re_b3 = (const float*)d_in[8];
    const float* rd_w1 = (const float*)d_in[9];
    const float* rd_b1 = (const float*)d_in[10];
    const float* rd_w2 = (const float*)d_in[11];
    const float* rd_b2 = (const float*)d_in[12];
    const float* rd_w3 = (const float*)d_in[13];
    const float* rd_b3 = (const float*)d_in[14];
    const float* me_w1 = (const float*)d_in[15];
    const float* me_b1 = (const float*)d_in[16];
    const float* me_w2 = (const float*)d_in[17];
    const float* me_b2 = (const float*)d_in[18];
    const float* me_w3 = (const float*)d_in[19];
    const float* me_b3 = (const float*)d_in[20];
    const float* md_w1 = (const float*)d_in[21];
    const float* md_b1 = (const float*)d_in[22];
    const float* md_w2 = (const float*)d_in[23];
    const float* md_b2 = (const float*)d_in[24];
    const float* md_w3 = (const float*)d_in[25];
    const float* md_b3 = (const float*)d_in[26];
    const float* lr_w  = (const float*)d_in[27];
    const float* lr_b  = (const float*)d_in[28];
    const float* lm_w  = (const float*)d_in[29];
    const float* lm_b  = (const float*)d_in[30];
    const int*   c2c   = (const int*)d_in[31];

    float* scratch = nullptr;
    cudaGetSymbolAddress((void**)&scratch, g_scratch);

    float* out    = (float*)d_out;
    float* rna    = out;                              // 2048*20000
    float* mirna  = out + 40960000;                   // 2048*2000
    float* logits = out + 45056000;                   // 2048*4095
    float* labels = out + 53442560;                   // 2048
    float* lproto = out + 53444608;                   // 2048*64
    float* lplab  = out + 53575680;                   // 2048

    // idempotent, called every invocation (no static guards allowed)
    cudaFuncSetAttribute(chain_kernel,
                         cudaFuncAttributeMaxDynamicSharedMemorySize,
                         CH_SMEM_BYTES);

    dim3 blk(256);

    // 1) encoder-L1 GEMMs, split-K=7 -> 448 blocks ~ one full wave at occ 3
    //    chunks are multiples of 16 (BK) so kStart stays float4-aligned:
    //    q: 6*2864 + 2816 = 20000 ; k: 6*288 + 272 = 2000
    bgemm_splitk<<<dim3(4, 16, ZS), blk>>>(omics_q, re_w1, scratch + O_PQ,
                                           NROWS, 200, 20000, 2864);
    bgemm_splitk<<<dim3(4, 16, ZS), blk>>>(omics_k, me_w1, scratch + O_PK,
                                           NROWS, 200, 2000, 288);
    // 2) split-K reduce + bias + relu (both jobs)
    {
        RedJobs rj;
        rj.P[0] = scratch + O_PQ; rj.bias[0] = re_b1; rj.C[0] = scratch + O_Q1;
        rj.P[1] = scratch + O_PK; rj.bias[1] = me_b1; rj.C[1] = scratch + O_K1;
        reduce_splitk<<<dim3(400, 1, 2), blk>>>(rj, NROWS, 200);
    }
    // 3) fused small chain (both sides)
    {
        ChainArgs ca;
        ca.s[0] = { scratch + O_Q1, re_w2, re_b2, re_w3, re_b3, lr_w, lr_b,
                    rd_w1, rd_b1, rd_w2, rd_b2,
                    scratch + O_Q, scratch + O_TQ, scratch + O_H2 };
        ca.s[1] = { scratch + O_K1, me_w2, me_b2, me_w3, me_b3, lm_w, lm_b,
                    md_w1, md_b1, md_w2, md_b2,
                    scratch + O_K, scratch + O_TK, scratch + O_HK2 };
        chain_kernel<<<dim3(32, 2), blk, CH_SMEM_BYTES>>>(ca);
    }
    // 4) decoder L3 (big-N GEMMs, sigmoid) — unchanged 128x64 path
    bgemm_act<<<dim3(313, 16), blk>>>(scratch + O_H2,  rd_w3, rd_b3, rna,
                                      NROWS, 20000, 200, 2);
    bgemm_act<<<dim3(32, 16),  blk>>>(scratch + O_HK2, md_w3, md_b3, mirna,
                                      NROWS, 2000, 200, 2);

    // 5) fused X (warp-per-row), contrastive logits, prototype logits
    fuse_X_kernel<<<256, 256>>>(scratch + O_Q, scratch + O_K,
                                scratch + O_TQ, scratch + O_TK, scratch + O_X);
    logits_kernel<<<dim3(32, 32), blk>>>(scratch + O_Q, scratch + O_K, logits);
    proto_kernel<<<512, blk>>>(scratch + O_X, protos, c2c, lproto, labels, lplab);
}